// round 1
// baseline (speedup 1.0000x reference)
#include <cuda_runtime.h>
#include <cuda_bf16.h>

// MHC layer fused kernel.
// Shapes: x [B=8192, N=4, C=4096] f32; out same. One block per batch row b.
// 512 threads/block; each thread owns 8 columns (two float4 slots, strided by
// 512 float4s) across all 4 streams -> 32 floats in registers, single pass.

#define N_STREAMS 4
#define C_DIM     4096
#define C4        (C_DIM / 4)      // 1024 float4 per (b, n) row
#define THREADS   512
#define EPS       1e-6f
#define SINKHORN_ITERS 3

__global__ __launch_bounds__(THREADS, 2)
void mhc_fused_kernel(const float* __restrict__ x,
                      const float* __restrict__ w,
                      const float* __restrict__ H_pre,
                      const float* __restrict__ H_post,
                      const float* __restrict__ H_res,
                      float* __restrict__ out)
{
    const int b   = blockIdx.x;
    const int tid = threadIdx.x;

    // ---- Load x row: 4 streams x 2 float4 slots, front-batched LDGs ----
    const float4* __restrict__ xr =
        reinterpret_cast<const float4*>(x) + (size_t)b * (N_STREAMS * C4);
    float4 v4[N_STREAMS][2];
    #pragma unroll
    for (int n = 0; n < N_STREAMS; n++) {
        v4[n][0] = xr[n * C4 + tid];
        v4[n][1] = xr[n * C4 + tid + THREADS];
    }

    // ---- Tiny params, computed redundantly per thread (registers) ----
    float hpre[N_STREAMS], hpost[N_STREAMS];
    #pragma unroll
    for (int i = 0; i < N_STREAMS; i++) {
        hpre[i]  = 1.0f / (1.0f + expf(-H_pre[i]));
        hpost[i] = 2.0f / (1.0f + expf(-H_post[i]));
    }
    float P[N_STREAMS][N_STREAMS];
    #pragma unroll
    for (int i = 0; i < N_STREAMS; i++)
        #pragma unroll
        for (int j = 0; j < N_STREAMS; j++)
            P[i][j] = expf(H_res[i * N_STREAMS + j]);
    #pragma unroll
    for (int it = 0; it < SINKHORN_ITERS; it++) {
        #pragma unroll
        for (int i = 0; i < N_STREAMS; i++) {
            float r = P[i][0] + P[i][1] + P[i][2] + P[i][3] + EPS;
            float ri = 1.0f / r;
            #pragma unroll
            for (int j = 0; j < N_STREAMS; j++) P[i][j] *= ri;
        }
        #pragma unroll
        for (int j = 0; j < N_STREAMS; j++) {
            float c = P[0][j] + P[1][j] + P[2][j] + P[3][j] + EPS;
            float ci = 1.0f / c;
            #pragma unroll
            for (int i = 0; i < N_STREAMS; i++) P[i][j] *= ci;
        }
    }

    // ---- View register float4s as scalar arrays ----
    float va[N_STREAMS][8];
    #pragma unroll
    for (int n = 0; n < N_STREAMS; n++) {
        va[n][0] = v4[n][0].x; va[n][1] = v4[n][0].y;
        va[n][2] = v4[n][0].z; va[n][3] = v4[n][0].w;
        va[n][4] = v4[n][1].x; va[n][5] = v4[n][1].y;
        va[n][6] = v4[n][1].z; va[n][7] = v4[n][1].w;
    }

    // ---- x_agg = sum_n sigmoid(H_pre[n]) * x[b,n,c]; bf16 round-trip ----
    float agg[8];
    float ss = 0.0f;
    #pragma unroll
    for (int e = 0; e < 8; e++) {
        float a = hpre[0] * va[0][e] + hpre[1] * va[1][e]
                + hpre[2] * va[2][e] + hpre[3] * va[3][e];
        a = __bfloat162float(__float2bfloat16_rn(a));
        agg[e] = a;
        ss += a * a;
    }

    // ---- Block reduction of sum of squares (512 threads = 16 warps) ----
    #pragma unroll
    for (int o = 16; o > 0; o >>= 1)
        ss += __shfl_xor_sync(0xffffffffu, ss, o);
    __shared__ float wsum[THREADS / 32];
    const int lane = tid & 31, wid = tid >> 5;
    if (lane == 0) wsum[wid] = ss;
    __syncthreads();
    float tot = 0.0f;
    #pragma unroll
    for (int i = 0; i < THREADS / 32; i++) tot += wsum[i];

    const float rinv = rsqrtf(tot * (1.0f / C_DIM) + EPS);

    // ---- y_norm = agg_bf * rinv * w[c] (w is L2-resident) ----
    const float4* __restrict__ w4 = reinterpret_cast<const float4*>(w);
    float4 wv0 = w4[tid];
    float4 wv1 = w4[tid + THREADS];
    float wa[8] = {wv0.x, wv0.y, wv0.z, wv0.w, wv1.x, wv1.y, wv1.z, wv1.w};

    float yn[8];
    #pragma unroll
    for (int e = 0; e < 8; e++) yn[e] = agg[e] * rinv * wa[e];

    // ---- out[b,i,c] = sum_j P[i][j]*x[b,j,c] + hpost[i]*y_norm ----
    float4* __restrict__ orow =
        reinterpret_cast<float4*>(out) + (size_t)b * (N_STREAMS * C4);
    #pragma unroll
    for (int i = 0; i < N_STREAMS; i++) {
        float o[8];
        #pragma unroll
        for (int e = 0; e < 8; e++) {
            o[e] = P[i][0] * va[0][e] + P[i][1] * va[1][e]
                 + P[i][2] * va[2][e] + P[i][3] * va[3][e]
                 + hpost[i] * yn[e];
        }
        float4 o0 = make_float4(o[0], o[1], o[2], o[3]);
        float4 o1 = make_float4(o[4], o[5], o[6], o[7]);
        orow[i * C4 + tid]           = o0;
        orow[i * C4 + tid + THREADS] = o1;
    }
}

extern "C" void kernel_launch(void* const* d_in, const int* in_sizes, int n_in,
                              void* d_out, int out_size)
{
    const float* x      = (const float*)d_in[0];
    const float* w      = (const float*)d_in[1];
    const float* H_pre  = (const float*)d_in[2];
    const float* H_post = (const float*)d_in[3];
    const float* H_res  = (const float*)d_in[4];
    float* out          = (float*)d_out;

    const int B = in_sizes[0] / (N_STREAMS * C_DIM);   // 8192
    mhc_fused_kernel<<<B, THREADS>>>(x, w, H_pre, H_post, H_res, out);
}